// round 9
// baseline (speedup 1.0000x reference)
#include <cuda_runtime.h>
#include <math.h>

#define NB 16
#define NN 1024
#define HD 256
#define ROWS (NB*NN)          // 16384
#define ZELEMS (ROWS*NN)      // 16777216

__device__ float g_Hcat[ROWS*768];
__device__ float g_g0[ROWS*HD];
__device__ float g_p1[ROWS*HD];
__device__ float g_p2[ROWS*HD];
__device__ float g_p3[ROWS*HD];
__device__ float g_p4[ROWS*HD];
__device__ float g_hp[ROWS*HD];
__device__ float g_tmp[ROWS*HD];
__device__ float g_mlp[ROWS*HD];
__device__ float g_Z0[ZELEMS];
__device__ float g_E[ZELEMS];      // exp(Z0 - rowmax)
__device__ float g_P[ZELEMS];
__device__ float g_dis[ROWS];
__device__ float g_rinv[ROWS];
__device__ float g_u[ROWS];
__device__ float g_v[ROWS];
__device__ float g_R[ROWS];        // row max of Z0
__device__ float g_cw[ROWS];       // exp(v - V) per batch-column
__device__ float g_y[ROWS];        // exp(R + u - U) per batch-row
__device__ float g_Vb[NB];
__device__ float g_Ub[NB];
__device__ float g_r[ROWS];
__device__ float g_c[ROWS];

__device__ __forceinline__ float leaky(float x) { return x >= 0.0f ? x : 0.01f * x; }

// packed f32x2 helpers (sm_103a; ptxas will not auto-fuse — PTX only)
__device__ __forceinline__ void ffma2(unsigned long long& d, unsigned long long a,
                                      unsigned long long b, unsigned long long c) {
    asm("fma.rn.f32x2 %0, %1, %2, %3;" : "=l"(d) : "l"(a), "l"(b), "l"(c));
}
__device__ __forceinline__ unsigned long long pack_dup(float x) {
    unsigned long long r;
    asm("mov.b64 %0, {%1, %1};" : "=l"(r) : "r"(__float_as_uint(x)));
    return r;
}
__device__ __forceinline__ void unpack2(float& lo, float& hi, unsigned long long p) {
    unsigned a, b;
    asm("mov.b64 {%0, %1}, %2;" : "=r"(a), "=r"(b) : "l"(p));
    lo = __uint_as_float(a); hi = __uint_as_float(b);
}

// ---------------- Threefry-2x32-20, key=(0,42) ----------------------------
// JAX partitionable scheme: element i uses counter (0, i); draw = out0 ^ out1.
__device__ __forceinline__ float tf_uniform(unsigned idx) {
    const unsigned ks0 = 0u, ks1 = 42u, ks2 = 42u ^ 0x1BD11BDAu;
    unsigned x0 = 0u + ks0;
    unsigned x1 = idx + ks1;
#define TFR(r) { x0 += x1; x1 = (x1 << (r)) | (x1 >> (32 - (r))); x1 ^= x0; }
    TFR(13) TFR(15) TFR(26) TFR(6)
    x0 += ks1; x1 += ks2 + 1u;
    TFR(17) TFR(29) TFR(16) TFR(24)
    x0 += ks2; x1 += ks0 + 2u;
    TFR(13) TFR(15) TFR(26) TFR(6)
    x0 += ks0; x1 += ks1 + 3u;
    TFR(17) TFR(29) TFR(16) TFR(24)
    x0 += ks1; x1 += ks2 + 4u;
    TFR(13) TFR(15) TFR(26) TFR(6)
    x0 += ks2; x1 += ks0 + 5u;
#undef TFR
    unsigned bits = x0 ^ x1;
    return __uint_as_float((bits >> 9) | 0x3f800000u) - 1.0f;
}

// ---------------- adj row stats ------------------------------------------
__global__ void k_adj_stats(const float* __restrict__ adj) {
    int row = blockIdx.x, t = threadIdx.x;
    const float4* a = (const float4*)(adj + (size_t)row * NN);
    float4 v = a[t];
    float s = v.x + v.y + v.z + v.w;
    __shared__ float sb[8];
    #pragma unroll
    for (int o = 16; o; o >>= 1) s += __shfl_xor_sync(0xffffffffu, s, o);
    if ((t & 31) == 0) sb[t >> 5] = s;
    __syncthreads();
    if (t == 0) {
        float tot = 0.0f;
        #pragma unroll
        for (int k = 0; k < 8; k++) tot += sb[k];
        g_dis[row]  = rsqrtf(tot + 1.0f);
        g_rinv[row] = 1.0f / tot;
    }
}

// ---------------- dense GEMM: C = epi(A @ W^T + bias) --------------------
__global__ __launch_bounds__(256, 2)
void k_gemm(const float* __restrict__ A, int ldA, int K,
            const float* __restrict__ W,
            const float* __restrict__ bias,
            float* __restrict__ C, int ldC, int epi) {
    __shared__ float As[8][128], Bs[8][128];
    int m0 = blockIdx.y * 128, n0 = blockIdx.x * 128;
    int tid = threadIdx.x, tx = tid & 15, ty = tid >> 4;
    int lr = tid >> 1, lk = (tid & 1) * 4;
    const float* Ap = A + (size_t)(m0 + lr) * ldA + lk;
    const float* Wp = W + (size_t)(n0 + lr) * K + lk;
    float acc[8][8];
    #pragma unroll
    for (int i = 0; i < 8; i++)
        #pragma unroll
        for (int j = 0; j < 8; j++) acc[i][j] = 0.0f;

    for (int k0 = 0; k0 < K; k0 += 8) {
        float4 av = *(const float4*)(Ap + k0);
        float4 wv = *(const float4*)(Wp + k0);
        __syncthreads();
        As[lk+0][lr]=av.x; As[lk+1][lr]=av.y; As[lk+2][lr]=av.z; As[lk+3][lr]=av.w;
        Bs[lk+0][lr]=wv.x; Bs[lk+1][lr]=wv.y; Bs[lk+2][lr]=wv.z; Bs[lk+3][lr]=wv.w;
        __syncthreads();
        #pragma unroll
        for (int kk = 0; kk < 8; kk++) {
            float4 a0 = *(const float4*)&As[kk][ty*8];
            float4 a1 = *(const float4*)&As[kk][ty*8+4];
            float4 b0 = *(const float4*)&Bs[kk][tx*8];
            float4 b1 = *(const float4*)&Bs[kk][tx*8+4];
            float ar[8] = {a0.x,a0.y,a0.z,a0.w,a1.x,a1.y,a1.z,a1.w};
            float br[8] = {b0.x,b0.y,b0.z,b0.w,b1.x,b1.y,b1.z,b1.w};
            #pragma unroll
            for (int i = 0; i < 8; i++)
                #pragma unroll
                for (int j = 0; j < 8; j++)
                    acc[i][j] = fmaf(ar[i], br[j], acc[i][j]);
        }
    }
    #pragma unroll
    for (int i = 0; i < 8; i++) {
        int row = m0 + ty * 8 + i;
        #pragma unroll
        for (int j = 0; j < 8; j++) {
            int n = n0 + tx * 8 + j;
            float val = acc[i][j] + bias[n];
            if (epi == 1) val = leaky(val);
            else if (epi == 2) {
                float lg = tanhf(val) * 40.0f;
                unsigned idx = (unsigned)row * 1024u + (unsigned)n;
                float uu = tf_uniform(idx);
                float inner = -logf(uu + 1e-20f);
                float nz = -logf(inner + 1e-20f) * 0.05f;
                val = (lg + nz) * 10.0f;
            }
            C[(size_t)row * ldC + n] = val;
        }
    }
}

// ---------------- adjacency GEMM, fused scaling, f32x2 mainloop ----------
__global__ __launch_bounds__(256, 2)
void k_adjmm(const float* __restrict__ adj, const float* __restrict__ X, int ldX,
             float* __restrict__ C, int mode) {
    int b = blockIdx.z;
    const float* Ab = adj + ((size_t)b << 20);
    const float* Xb = X + (size_t)b * NN * ldX;
    float* Cb = C + ((size_t)b << 18);
    const float* cs = g_dis + (b << 10);
    const float* rs = (mode == 0 ? g_dis : g_rinv) + (b << 10);
    __shared__ float As[8][128], Bs[8][128];
    int m0 = blockIdx.y * 128, n0 = blockIdx.x * 128;
    int tid = threadIdx.x, tx = tid & 15, ty = tid >> 4;
    int lr = tid >> 1, lk = (tid & 1) * 4;
    int jb = tid >> 5, jn = (tid & 31) * 4;
    const float* Ap = Ab + (size_t)(m0 + lr) * NN + lk;
    unsigned long long acc2[8][4];
    #pragma unroll
    for (int i = 0; i < 8; i++)
        #pragma unroll
        for (int j = 0; j < 4; j++) acc2[i][j] = 0ull;

    for (int k0 = 0; k0 < NN; k0 += 8) {
        float4 av = *(const float4*)(Ap + k0);
        float4 xv = *(const float4*)(Xb + (size_t)(k0 + jb) * ldX + n0 + jn);
        float sc = (mode == 0) ? cs[k0 + jb] : 1.0f;
        __syncthreads();
        As[lk+0][lr]=av.x; As[lk+1][lr]=av.y; As[lk+2][lr]=av.z; As[lk+3][lr]=av.w;
        Bs[jb][jn+0]=xv.x*sc; Bs[jb][jn+1]=xv.y*sc; Bs[jb][jn+2]=xv.z*sc; Bs[jb][jn+3]=xv.w*sc;
        __syncthreads();
        #pragma unroll
        for (int kk = 0; kk < 8; kk++) {
            float4 a0 = *(const float4*)&As[kk][ty*8];
            float4 a1 = *(const float4*)&As[kk][ty*8+4];
            float ar[8] = {a0.x,a0.y,a0.z,a0.w,a1.x,a1.y,a1.z,a1.w};
            const unsigned long long* bp =
                (const unsigned long long*)&Bs[kk][tx*8];  // 32B-aligned
            unsigned long long b2_0 = bp[0], b2_1 = bp[1], b2_2 = bp[2], b2_3 = bp[3];
            #pragma unroll
            for (int i = 0; i < 8; i++) {
                unsigned long long a2 = pack_dup(ar[i]);
                ffma2(acc2[i][0], a2, b2_0, acc2[i][0]);
                ffma2(acc2[i][1], a2, b2_1, acc2[i][1]);
                ffma2(acc2[i][2], a2, b2_2, acc2[i][2]);
                ffma2(acc2[i][3], a2, b2_3, acc2[i][3]);
            }
        }
    }
    #pragma unroll
    for (int i = 0; i < 8; i++) {
        int row = m0 + ty * 8 + i;
        float rsc = rs[row];
        #pragma unroll
        for (int jp = 0; jp < 4; jp++) {
            float aL, aH;
            unpack2(aL, aH, acc2[i][jp]);
            #pragma unroll
            for (int h = 0; h < 2; h++) {
                int n = n0 + tx * 8 + jp * 2 + h;
                float a = h ? aH : aL;
                float self = Xb[(size_t)row * ldX + n];
                float val;
                if (mode == 0) val = leaky(rsc * a + rsc * rsc * self);
                else           val = 0.5f * (rsc * a + self);
                Cb[((size_t)row << 8) + n] = val;
            }
        }
    }
}

// ---------------- attention combine (channel softmax; x-term cancels) ----
__global__ void k_attn(const float* __restrict__ Xl, const float* __restrict__ a2) {
    int r = blockIdx.x, d = threadIdx.x;
    size_t o = ((size_t)r << 8) + d;
    float x  = Xl[(size_t)r * 768 + d];
    float g0 = g_g0[o], p1 = g_p1[o], p2 = g_p2[o], p4 = g_p4[o];
    float c1 = fabsf(x - p1), c2 = fabsf(p1 - p2), c3 = fabsf(p2 - p4);
    float av = a2[d];
    float s0 = fmaxf(g0, 0.0f) * av, s1 = c1 * av, s2 = c2 * av, s3 = c3 * av;
    __shared__ float red[4][8];
    #pragma unroll
    for (int off = 16; off; off >>= 1) {
        s0 += __shfl_xor_sync(0xffffffffu, s0, off);
        s1 += __shfl_xor_sync(0xffffffffu, s1, off);
        s2 += __shfl_xor_sync(0xffffffffu, s2, off);
        s3 += __shfl_xor_sync(0xffffffffu, s3, off);
    }
    if ((d & 31) == 0) { int w = d >> 5; red[0][w]=s0; red[1][w]=s1; red[2][w]=s2; red[3][w]=s3; }
    __syncthreads();
    float t0=0,t1=0,t2=0,t3=0;
    #pragma unroll
    for (int k = 0; k < 8; k++) { t0+=red[0][k]; t1+=red[1][k]; t2+=red[2][k]; t3+=red[3][k]; }
    float mx = fmaxf(fmaxf(t0,t1), fmaxf(t2,t3));
    float e0 = __expf(t0-mx), e1 = __expf(t1-mx), e2 = __expf(t2-mx), e3 = __expf(t3-mx);
    float inv = 0.25f / (e0+e1+e2+e3);
    g_hp[o] = inv * (e0*g0 + e1*c1 + e2*c2 + e3*c3);
}

// ---------------- Sinkhorn: linear-domain with log-domain fallback -------
__global__ void k_prep(const float* __restrict__ Z) {
    int r = blockIdx.x, t = threadIdx.x;
    const float4* z4 = (const float4*)(Z + ((size_t)r << 10));
    float4 z = z4[t];
    float m = fmaxf(fmaxf(z.x, z.y), fmaxf(z.z, z.w));
    __shared__ float sb[8]; __shared__ float sM;
    #pragma unroll
    for (int o = 16; o; o >>= 1) m = fmaxf(m, __shfl_xor_sync(0xffffffffu, m, o));
    if ((t & 31) == 0) sb[t >> 5] = m;
    __syncthreads();
    if (t == 0) {
        float M = sb[0];
        #pragma unroll
        for (int k = 1; k < 8; k++) M = fmaxf(M, sb[k]);
        sM = M; g_R[r] = M;
    }
    __syncthreads();
    float M = sM;
    float4 e;
    e.x = __expf(z.x - M); e.y = __expf(z.y - M);
    e.z = __expf(z.z - M); e.w = __expf(z.w - M);
    ((float4*)(g_E + ((size_t)r << 10)))[t] = e;
}

__global__ void k_wexp() {
    int b = blockIdx.x, t = threadIdx.x;
    float4 v = ((const float4*)(g_v + (b << 10)))[t];
    float m = fmaxf(fmaxf(v.x, v.y), fmaxf(v.z, v.w));
    __shared__ float sb[8]; __shared__ float sV;
    #pragma unroll
    for (int o = 16; o; o >>= 1) m = fmaxf(m, __shfl_xor_sync(0xffffffffu, m, o));
    if ((t & 31) == 0) sb[t >> 5] = m;
    __syncthreads();
    if (t == 0) {
        float V = sb[0];
        #pragma unroll
        for (int k = 1; k < 8; k++) V = fmaxf(V, sb[k]);
        sV = V; g_Vb[b] = V;
    }
    __syncthreads();
    float V = sV;
    float4 w;
    w.x = __expf(v.x - V); w.y = __expf(v.y - V);
    w.z = __expf(v.z - V); w.w = __expf(v.w - V);
    ((float4*)(g_cw + (b << 10)))[t] = w;
}

__global__ void k_srow(const float* __restrict__ Z) {
    int r = blockIdx.x, b = r >> 10, t = threadIdx.x;
    float4 e = ((const float4*)(g_E + ((size_t)r << 10)))[t];
    float4 w = ((const float4*)(g_cw + (b << 10)))[t];
    float s = e.x*w.x + e.y*w.y + e.z*w.z + e.w*w.w;
    __shared__ float sb[8]; __shared__ float sS;
    #pragma unroll
    for (int o = 16; o; o >>= 1) s += __shfl_xor_sync(0xffffffffu, s, o);
    if ((t & 31) == 0) sb[t >> 5] = s;
    __syncthreads();
    if (t == 0) {
        float S = 0.0f;
        #pragma unroll
        for (int k = 0; k < 8; k++) S += sb[k];
        sS = S;
    }
    __syncthreads();
    float S = sS;
    if (S >= 1e-30f) {
        if (t == 0) g_u[r] = -(g_R[r] + g_Vb[b] + logf(S));
        return;
    }
    float4 z = ((const float4*)(Z + ((size_t)r << 10)))[t];
    float4 v = ((const float4*)(g_v + (b << 10)))[t];
    float a0 = z.x+v.x, a1 = z.y+v.y, a2 = z.z+v.z, a3 = z.w+v.w;
    float m = fmaxf(fmaxf(a0, a1), fmaxf(a2, a3));
    #pragma unroll
    for (int o = 16; o; o >>= 1) m = fmaxf(m, __shfl_xor_sync(0xffffffffu, m, o));
    if ((t & 31) == 0) sb[t >> 5] = m;
    __syncthreads();
    float M = sb[0];
    #pragma unroll
    for (int k = 1; k < 8; k++) M = fmaxf(M, sb[k]);
    __syncthreads();
    float s2 = __expf(a0-M) + __expf(a1-M) + __expf(a2-M) + __expf(a3-M);
    #pragma unroll
    for (int o = 16; o; o >>= 1) s2 += __shfl_xor_sync(0xffffffffu, s2, o);
    if ((t & 31) == 0) sb[t >> 5] = s2;
    __syncthreads();
    if (t == 0) {
        float S2 = 0.0f;
        #pragma unroll
        for (int k = 0; k < 8; k++) S2 += sb[k];
        g_u[r] = -(M + logf(S2));
    }
}

__global__ void k_yexp() {
    int b = blockIdx.x, t = threadIdx.x;
    float4 R = ((const float4*)(g_R + (b << 10)))[t];
    float4 u = ((const float4*)(g_u + (b << 10)))[t];
    float4 a; a.x = R.x+u.x; a.y = R.y+u.y; a.z = R.z+u.z; a.w = R.w+u.w;
    float m = fmaxf(fmaxf(a.x, a.y), fmaxf(a.z, a.w));
    __shared__ float sb[8]; __shared__ float sU;
    #pragma unroll
    for (int o = 16; o; o >>= 1) m = fmaxf(m, __shfl_xor_sync(0xffffffffu, m, o));
    if ((t & 31) == 0) sb[t >> 5] = m;
    __syncthreads();
    if (t == 0) {
        float U = sb[0];
        #pragma unroll
        for (int k = 1; k < 8; k++) U = fmaxf(U, sb[k]);
        sU = U; g_Ub[b] = U;
    }
    __syncthreads();
    float U = sU;
    float4 y;
    y.x = __expf(a.x - U); y.y = __expf(a.y - U);
    y.z = __expf(a.z - U); y.w = __expf(a.w - U);
    ((float4*)(g_y + (b << 10)))[t] = y;
}

__global__ void k_scol(const float* __restrict__ Z) {
    int b = blockIdx.y;
    int t = threadIdx.x, lane = t & 31, w = t >> 5;
    int col = blockIdx.x * 32 + lane;
    const float* Eb = g_E + ((size_t)b << 20);
    const float* yb = g_y + (b << 10);
    __shared__ float sm[8][32];
    __shared__ float tcol[32];
    __shared__ float mcol[32];
    float s = 0.0f;
    for (int i = w; i < NN; i += 8)
        s += Eb[((size_t)i << 10) + col] * yb[i];
    sm[w][lane] = s;
    __syncthreads();
    if (w == 0) {
        float ss = 0.0f;
        #pragma unroll
        for (int k = 0; k < 8; k++) ss += sm[k][lane];
        tcol[lane] = ss;
    }
    __syncthreads();
    float T = tcol[lane];
    float U = g_Ub[b];
    int anyslow = __syncthreads_or(T < 1e-30f);
    if (!anyslow) {
        if (w == 0) g_v[(b << 10) + col] = -(U + logf(T));
        return;
    }
    const float* Zb = Z + ((size_t)b << 20);
    const float* ub = g_u + (b << 10);
    float m = -1e30f;
    for (int i = w; i < NN; i += 8)
        m = fmaxf(m, Zb[((size_t)i << 10) + col] + ub[i]);
    sm[w][lane] = m;
    __syncthreads();
    if (w == 0) {
        float mm = sm[0][lane];
        #pragma unroll
        for (int k = 1; k < 8; k++) mm = fmaxf(mm, sm[k][lane]);
        mcol[lane] = mm;
    }
    __syncthreads();
    float M = mcol[lane];
    float s2 = 0.0f;
    for (int i = w; i < NN; i += 8)
        s2 += __expf(Zb[((size_t)i << 10) + col] + ub[i] - M);
    sm[w][lane] = s2;
    __syncthreads();
    if (w == 0) {
        float ss2 = 0.0f;
        #pragma unroll
        for (int k = 0; k < 8; k++) ss2 += sm[k][lane];
        float res = (T < 1e-30f) ? -(M + logf(ss2)) : -(U + logf(T));
        g_v[(b << 10) + col] = res;
    }
}

// ---------------- finalization -------------------------------------------
__global__ void k_final_row(const float* __restrict__ Z) {
    int r = blockIdx.x, b = r >> 10, t = threadIdx.x;
    const float4* z4 = (const float4*)(Z + ((size_t)r << 10));
    const float4* v4 = (const float4*)(g_v + (b << 10));
    float uu = g_u[r];
    float4 z = z4[t], v = v4[t], e;
    e.x = __expf(z.x + uu + v.x); e.y = __expf(z.y + uu + v.y);
    e.z = __expf(z.z + uu + v.z); e.w = __expf(z.w + uu + v.w);
    ((float4*)(g_P + ((size_t)r << 10)))[t] = e;
    float s = e.x + e.y + e.z + e.w;
    __shared__ float sb[8];
    #pragma unroll
    for (int o = 16; o; o >>= 1) s += __shfl_xor_sync(0xffffffffu, s, o);
    if ((t & 31) == 0) sb[t >> 5] = s;
    __syncthreads();
    if (t == 0) {
        float S = 0.0f;
        #pragma unroll
        for (int k = 0; k < 8; k++) S += sb[k];
        g_r[r] = 1.0f / S;
    }
}

__global__ void k_final_col() {
    int b = blockIdx.y;
    int lane = threadIdx.x & 31, w = threadIdx.x >> 5;
    int col = blockIdx.x * 32 + lane;
    const float* Pb = g_P + ((size_t)b << 20);
    const float* rb = g_r + (b << 10);
    __shared__ float sm[8][32];
    float s = 0.0f;
    for (int i = w; i < NN; i += 8)
        s += Pb[((size_t)i << 10) + col] * rb[i];
    sm[w][lane] = s;
    __syncthreads();
    if (w == 0) {
        float ss = 0.0f;
        #pragma unroll
        for (int k = 0; k < 8; k++) ss += sm[k][lane];
        g_c[(b << 10) + col] = 1.0f / ss;
    }
}

__global__ void k_writeP(float* __restrict__ outp) {
    int r = blockIdx.x, b = r >> 10, t = threadIdx.x;
    float ri = g_r[r];
    float4 pv = ((const float4*)(g_P + ((size_t)r << 10)))[t];
    float4 cv = ((const float4*)(g_c + (b << 10)))[t];
    float4 o;
    o.x = pv.x * ri * cv.x; o.y = pv.y * ri * cv.y;
    o.z = pv.z * ri * cv.z; o.w = pv.w * ri * cv.w;
    ((float4*)outp)[((size_t)r << 8) + t] = o;
}

__global__ void k_copyZ(float* __restrict__ outp) {
    int r = blockIdx.x, t = threadIdx.x;
    float4 z = ((const float4*)(g_Z0 + ((size_t)r << 10)))[t];
    ((float4*)outp)[((size_t)r << 8) + t] = z;
}

__global__ void k_zero(float* __restrict__ p) {
    p[blockIdx.x * 1024 + threadIdx.x] = 0.0f;
}

// ---------------- host ----------------------------------------------------
extern "C" void kernel_launch(void* const* d_in, const int* in_sizes, int n_in,
                              void* d_out, int out_size) {
    const float* X    = (const float*)d_in[0];
    const float* adj  = (const float*)d_in[1];
    const float* w_in = (const float*)d_in[2];
    const float* b_in = (const float*)d_in[3];
    const float* cw1  = (const float*)d_in[4];
    const float* cb1  = (const float*)d_in[5];
    const float* cw2  = (const float*)d_in[6];
    const float* cb2  = (const float*)d_in[7];
    const float* ca   = (const float*)d_in[8];
    const float* m1w  = (const float*)d_in[9];
    const float* m1b  = (const float*)d_in[10];
    const float* m2w  = (const float*)d_in[11];
    const float* m2b  = (const float*)d_in[12];
    float* out = (float*)d_out;

    float *hcat, *g0, *p1, *p2, *p3, *p4, *hp, *tmp, *mlp, *Z0, *vv;
    cudaGetSymbolAddress((void**)&hcat, g_Hcat);
    cudaGetSymbolAddress((void**)&g0,   g_g0);
    cudaGetSymbolAddress((void**)&p1,   g_p1);
    cudaGetSymbolAddress((void**)&p2,   g_p2);
    cudaGetSymbolAddress((void**)&p3,   g_p3);
    cudaGetSymbolAddress((void**)&p4,   g_p4);
    cudaGetSymbolAddress((void**)&hp,   g_hp);
    cudaGetSymbolAddress((void**)&tmp,  g_tmp);
    cudaGetSymbolAddress((void**)&mlp,  g_mlp);
    cudaGetSymbolAddress((void**)&Z0,   g_Z0);
    cudaGetSymbolAddress((void**)&vv,   g_v);

    dim3 gN(2, 128);          // N=256 outputs, M=16384
    dim3 gZ(8, 128);          // N=1024 outputs
    dim3 gA(2, 8, 16);        // adj GEMM per batch
    dim3 gC(32, 16);          // column passes

    k_adj_stats<<<ROWS, 256>>>(adj);
    k_gemm<<<gN, 256>>>(X, 128, 128, w_in, b_in, hcat, 768, 0);

    for (int l = 0; l < 2; l++) {
        const float* Xl = hcat + l * 256;
        k_adjmm<<<gA, 256>>>(adj, Xl, 768, g0, 0);
        k_adjmm<<<gA, 256>>>(adj, Xl, 768, p1, 1);
        k_adjmm<<<gA, 256>>>(adj, p1, 256, p2, 1);
        k_adjmm<<<gA, 256>>>(adj, p2, 256, p3, 1);
        k_adjmm<<<gA, 256>>>(adj, p3, 256, p4, 1);
        k_attn<<<ROWS, 256>>>(Xl, ca + l * 512 + 256);
        k_gemm<<<gN, 256>>>(hp, 256, 256, cw1 + l * 65536, cb1 + l * 256, tmp, 256, 1);
        k_gemm<<<gN, 256>>>(tmp, 256, 256, cw2 + l * 65536, cb2 + l * 256,
                            hcat + (l + 1) * 256, 768, 1);
    }
    k_gemm<<<gN, 256>>>(hcat, 768, 768, m1w, m1b, mlp, 256, 1);
    k_gemm<<<gZ, 256>>>(mlp, 256, 256, m2w, m2b, Z0, 1024, 2);

    // Sinkhorn (linear-domain iterations over E with potentials)
    k_zero<<<16, 1024>>>(vv);
    k_prep<<<ROWS, 256>>>(Z0);
    for (int it = 0; it < 20; it++) {
        k_wexp<<<NB, 256>>>();
        k_srow<<<ROWS, 256>>>(Z0);
        k_yexp<<<NB, 256>>>();
        k_scol<<<gC, 256>>>(Z0);
    }
    k_final_row<<<ROWS, 256>>>(Z0);
    k_final_col<<<gC, 256>>>();
    k_writeP<<<ROWS, 256>>>(out);
    if (out_size >= 2 * ZELEMS)
        k_copyZ<<<ROWS, 256>>>(out + ZELEMS);
}

// round 15
// speedup vs baseline: 1.0289x; 1.0289x over previous
#include <cuda_runtime.h>
#include <math.h>

#define NB 16
#define NN 1024
#define HD 256
#define ROWS (NB*NN)          // 16384
#define ZELEMS (ROWS*NN)      // 16777216

__device__ float g_Hcat[ROWS*768];
__device__ float g_g0[ROWS*HD];
__device__ float g_p1[ROWS*HD];
__device__ float g_p2[ROWS*HD];
__device__ float g_p3[ROWS*HD];
__device__ float g_p4[ROWS*HD];
__device__ float g_hp[ROWS*HD];
__device__ float g_tmp[ROWS*HD];
__device__ float g_mlp[ROWS*HD];
__device__ float g_Z0[ZELEMS];
__device__ float g_E[ZELEMS];      // exp(Z0 - rowmax)
__device__ float g_P[ZELEMS];
__device__ float g_dis[ROWS];
__device__ float g_rinv[ROWS];
__device__ float g_u[ROWS];
__device__ float g_v[ROWS];
__device__ float g_R[ROWS];
__device__ float g_cw[ROWS];
__device__ float g_y[ROWS];
__device__ float g_Vb[NB];
__device__ float g_Ub[NB];
__device__ float g_r[ROWS];
__device__ float g_c[ROWS];

__device__ __forceinline__ float leaky(float x) { return x >= 0.0f ? x : 0.01f * x; }

// packed f32x2 helpers
__device__ __forceinline__ void ffma2(unsigned long long& d, unsigned long long a,
                                      unsigned long long b, unsigned long long c) {
    asm("fma.rn.f32x2 %0, %1, %2, %3;" : "=l"(d) : "l"(a), "l"(b), "l"(c));
}
__device__ __forceinline__ unsigned long long pack_dup(float x) {
    unsigned long long r;
    asm("mov.b64 %0, {%1, %1};" : "=l"(r) : "r"(__float_as_uint(x)));
    return r;
}
__device__ __forceinline__ unsigned long long pack2f(float x, float y) {
    unsigned long long r;
    asm("mov.b64 %0, {%1, %2};" : "=l"(r) : "r"(__float_as_uint(x)), "r"(__float_as_uint(y)));
    return r;
}
__device__ __forceinline__ void unpack2(float& lo, float& hi, unsigned long long p) {
    unsigned a, b;
    asm("mov.b64 {%0, %1}, %2;" : "=r"(a), "=r"(b) : "l"(p));
    lo = __uint_as_float(a); hi = __uint_as_float(b);
}

// ---------------- Threefry-2x32-20, key=(0,42), partitionable -------------
__device__ __forceinline__ float tf_uniform(unsigned idx) {
    const unsigned ks0 = 0u, ks1 = 42u, ks2 = 42u ^ 0x1BD11BDAu;
    unsigned x0 = 0u + ks0;
    unsigned x1 = idx + ks1;
#define TFR(r) { x0 += x1; x1 = (x1 << (r)) | (x1 >> (32 - (r))); x1 ^= x0; }
    TFR(13) TFR(15) TFR(26) TFR(6)
    x0 += ks1; x1 += ks2 + 1u;
    TFR(17) TFR(29) TFR(16) TFR(24)
    x0 += ks2; x1 += ks0 + 2u;
    TFR(13) TFR(15) TFR(26) TFR(6)
    x0 += ks0; x1 += ks1 + 3u;
    TFR(17) TFR(29) TFR(16) TFR(24)
    x0 += ks1; x1 += ks2 + 4u;
    TFR(13) TFR(15) TFR(26) TFR(6)
    x0 += ks2; x1 += ks0 + 5u;
#undef TFR
    unsigned bits = x0 ^ x1;
    return __uint_as_float((bits >> 9) | 0x3f800000u) - 1.0f;
}

// ---------------- adj row stats ------------------------------------------
__global__ void k_adj_stats(const float* __restrict__ adj) {
    int row = blockIdx.x, t = threadIdx.x;
    const float4* a = (const float4*)(adj + (size_t)row * NN);
    float4 v = a[t];
    float s = v.x + v.y + v.z + v.w;
    __shared__ float sb[8];
    #pragma unroll
    for (int o = 16; o; o >>= 1) s += __shfl_xor_sync(0xffffffffu, s, o);
    if ((t & 31) == 0) sb[t >> 5] = s;
    __syncthreads();
    if (t == 0) {
        float tot = 0.0f;
        #pragma unroll
        for (int k = 0; k < 8; k++) tot += sb[k];
        g_dis[row]  = rsqrtf(tot + 1.0f);
        g_rinv[row] = 1.0f / tot;
    }
}

// ---------------- dense GEMM: C = epi(A @ W^T + bias), f32x2 + pipeline ---
__global__ __launch_bounds__(256, 2)
void k_gemm(const float* __restrict__ A, int ldA, int K,
            const float* __restrict__ W,
            const float* __restrict__ bias,
            float* __restrict__ C, int ldC, int epi) {
    __shared__ float As[8][128], Bs[8][128];
    int m0 = blockIdx.y * 128, n0 = blockIdx.x * 128;
    int tid = threadIdx.x, tx = tid & 15, ty = tid >> 4;
    int lr = tid >> 1, lk = (tid & 1) * 4;
    const float* Ap = A + (size_t)(m0 + lr) * ldA + lk;
    const float* Wp = W + (size_t)(n0 + lr) * K + lk;
    unsigned long long acc2[8][4];
    #pragma unroll
    for (int i = 0; i < 8; i++)
        #pragma unroll
        for (int j = 0; j < 4; j++) acc2[i][j] = 0ull;

    float4 av = *(const float4*)(Ap);
    float4 wv = *(const float4*)(Wp);
    for (int k0 = 0; k0 < K; k0 += 8) {
        __syncthreads();
        As[lk+0][lr]=av.x; As[lk+1][lr]=av.y; As[lk+2][lr]=av.z; As[lk+3][lr]=av.w;
        Bs[lk+0][lr]=wv.x; Bs[lk+1][lr]=wv.y; Bs[lk+2][lr]=wv.z; Bs[lk+3][lr]=wv.w;
        __syncthreads();
        if (k0 + 8 < K) {
            av = *(const float4*)(Ap + k0 + 8);
            wv = *(const float4*)(Wp + k0 + 8);
        }
        #pragma unroll
        for (int kk = 0; kk < 8; kk++) {
            float4 a0 = *(const float4*)&As[kk][ty*8];
            float4 a1 = *(const float4*)&As[kk][ty*8+4];
            float4 b0 = *(const float4*)&Bs[kk][tx*8];
            float4 b1 = *(const float4*)&Bs[kk][tx*8+4];
            float ar[8] = {a0.x,a0.y,a0.z,a0.w,a1.x,a1.y,a1.z,a1.w};
            unsigned long long b2_0 = pack2f(b0.x, b0.y);
            unsigned long long b2_1 = pack2f(b0.z, b0.w);
            unsigned long long b2_2 = pack2f(b1.x, b1.y);
            unsigned long long b2_3 = pack2f(b1.z, b1.w);
            #pragma unroll
            for (int i = 0; i < 8; i++) {
                unsigned long long a2 = pack_dup(ar[i]);
                ffma2(acc2[i][0], a2, b2_0, acc2[i][0]);
                ffma2(acc2[i][1], a2, b2_1, acc2[i][1]);
                ffma2(acc2[i][2], a2, b2_2, acc2[i][2]);
                ffma2(acc2[i][3], a2, b2_3, acc2[i][3]);
            }
        }
    }
    #pragma unroll
    for (int i = 0; i < 8; i++) {
        int row = m0 + ty * 8 + i;
        #pragma unroll
        for (int jp = 0; jp < 4; jp++) {
            float aL, aH;
            unpack2(aL, aH, acc2[i][jp]);
            #pragma unroll
            for (int h = 0; h < 2; h++) {
                int n = n0 + tx * 8 + jp * 2 + h;
                float val = (h ? aH : aL) + bias[n];
                if (epi == 1) val = leaky(val);
                else if (epi == 2) {
                    float lg = tanhf(val) * 40.0f;
                    unsigned idx = (unsigned)row * 1024u + (unsigned)n;
                    float uu = tf_uniform(idx);
                    float inner = -logf(uu + 1e-20f);
                    float nz = -logf(inner + 1e-20f) * 0.05f;
                    val = (lg + nz) * 10.0f;
                }
                C[(size_t)row * ldC + n] = val;
            }
        }
    }
}

// ---------------- adjacency GEMM, fused scaling, f32x2 + pipeline --------
__global__ __launch_bounds__(256, 2)
void k_adjmm(const float* __restrict__ adj, const float* __restrict__ X, int ldX,
             float* __restrict__ C, int mode) {
    int b = blockIdx.z;
    const float* Ab = adj + ((size_t)b << 20);
    const float* Xb = X + (size_t)b * NN * ldX;
    float* Cb = C + ((size_t)b << 18);
    const float* cs = g_dis + (b << 10);
    const float* rs = (mode == 0 ? g_dis : g_rinv) + (b << 10);
    __shared__ float As[8][128], Bs[8][128];
    int m0 = blockIdx.y * 128, n0 = blockIdx.x * 128;
    int tid = threadIdx.x, tx = tid & 15, ty = tid >> 4;
    int lr = tid >> 1, lk = (tid & 1) * 4;
    int jb = tid >> 5, jn = (tid & 31) * 4;
    const float* Ap = Ab + (size_t)(m0 + lr) * NN + lk;
    unsigned long long acc2[8][4];
    #pragma unroll
    for (int i = 0; i < 8; i++)
        #pragma unroll
        for (int j = 0; j < 4; j++) acc2[i][j] = 0ull;

    float4 av = *(const float4*)(Ap);
    float4 xv = *(const float4*)(Xb + (size_t)jb * ldX + n0 + jn);
    float sc = (mode == 0) ? cs[jb] : 1.0f;
    for (int k0 = 0; k0 < NN; k0 += 8) {
        __syncthreads();
        As[lk+0][lr]=av.x; As[lk+1][lr]=av.y; As[lk+2][lr]=av.z; As[lk+3][lr]=av.w;
        Bs[jb][jn+0]=xv.x*sc; Bs[jb][jn+1]=xv.y*sc; Bs[jb][jn+2]=xv.z*sc; Bs[jb][jn+3]=xv.w*sc;
        __syncthreads();
        if (k0 + 8 < NN) {
            av = *(const float4*)(Ap + k0 + 8);
            xv = *(const float4*)(Xb + (size_t)(k0 + 8 + jb) * ldX + n0 + jn);
            sc = (mode == 0) ? cs[k0 + 8 + jb] : 1.0f;
        }
        #pragma unroll
        for (int kk = 0; kk < 8; kk++) {
            float4 a0 = *(const float4*)&As[kk][ty*8];
            float4 a1 = *(const float4*)&As[kk][ty*8+4];
            float4 b0 = *(const float4*)&Bs[kk][tx*8];
            float4 b1 = *(const float4*)&Bs[kk][tx*8+4];
            float ar[8] = {a0.x,a0.y,a0.z,a0.w,a1.x,a1.y,a1.z,a1.w};
            unsigned long long b2_0 = pack2f(b0.x, b0.y);
            unsigned long long b2_1 = pack2f(b0.z, b0.w);
            unsigned long long b2_2 = pack2f(b1.x, b1.y);
            unsigned long long b2_3 = pack2f(b1.z, b1.w);
            #pragma unroll
            for (int i = 0; i < 8; i++) {
                unsigned long long a2 = pack_dup(ar[i]);
                ffma2(acc2[i][0], a2, b2_0, acc2[i][0]);
                ffma2(acc2[i][1], a2, b2_1, acc2[i][1]);
                ffma2(acc2[i][2], a2, b2_2, acc2[i][2]);
                ffma2(acc2[i][3], a2, b2_3, acc2[i][3]);
            }
        }
    }
    #pragma unroll
    for (int i = 0; i < 8; i++) {
        int row = m0 + ty * 8 + i;
        float rsc = rs[row];
        #pragma unroll
        for (int jp = 0; jp < 4; jp++) {
            float aL, aH;
            unpack2(aL, aH, acc2[i][jp]);
            #pragma unroll
            for (int h = 0; h < 2; h++) {
                int n = n0 + tx * 8 + jp * 2 + h;
                float a = h ? aH : aL;
                float self = Xb[(size_t)row * ldX + n];
                float val;
                if (mode == 0) val = leaky(rsc * a + rsc * rsc * self);
                else           val = 0.5f * (rsc * a + self);
                Cb[((size_t)row << 8) + n] = val;
            }
        }
    }
}

// ---------------- attention combine --------------------------------------
__global__ void k_attn(const float* __restrict__ Xl, const float* __restrict__ a2) {
    int r = blockIdx.x, d = threadIdx.x;
    size_t o = ((size_t)r << 8) + d;
    float x  = Xl[(size_t)r * 768 + d];
    float g0 = g_g0[o], p1 = g_p1[o], p2 = g_p2[o], p4 = g_p4[o];
    float c1 = fabsf(x - p1), c2 = fabsf(p1 - p2), c3 = fabsf(p2 - p4);
    float av = a2[d];
    float s0 = fmaxf(g0, 0.0f) * av, s1 = c1 * av, s2 = c2 * av, s3 = c3 * av;
    __shared__ float red[4][8];
    #pragma unroll
    for (int off = 16; off; off >>= 1) {
        s0 += __shfl_xor_sync(0xffffffffu, s0, off);
        s1 += __shfl_xor_sync(0xffffffffu, s1, off);
        s2 += __shfl_xor_sync(0xffffffffu, s2, off);
        s3 += __shfl_xor_sync(0xffffffffu, s3, off);
    }
    if ((d & 31) == 0) { int w = d >> 5; red[0][w]=s0; red[1][w]=s1; red[2][w]=s2; red[3][w]=s3; }
    __syncthreads();
    float t0=0,t1=0,t2=0,t3=0;
    #pragma unroll
    for (int k = 0; k < 8; k++) { t0+=red[0][k]; t1+=red[1][k]; t2+=red[2][k]; t3+=red[3][k]; }
    float mx = fmaxf(fmaxf(t0,t1), fmaxf(t2,t3));
    float e0 = __expf(t0-mx), e1 = __expf(t1-mx), e2 = __expf(t2-mx), e3 = __expf(t3-mx);
    float inv = 0.25f / (e0+e1+e2+e3);
    g_hp[o] = inv * (e0*g0 + e1*c1 + e2*c2 + e3*c3);
}

// ---------------- Sinkhorn: linear-domain with log-domain fallback -------
__global__ void k_prep(const float* __restrict__ Z) {
    int r = blockIdx.x, t = threadIdx.x;
    const float4* z4 = (const float4*)(Z + ((size_t)r << 10));
    float4 z = z4[t];
    float m = fmaxf(fmaxf(z.x, z.y), fmaxf(z.z, z.w));
    __shared__ float sb[8]; __shared__ float sM;
    #pragma unroll
    for (int o = 16; o; o >>= 1) m = fmaxf(m, __shfl_xor_sync(0xffffffffu, m, o));
    if ((t & 31) == 0) sb[t >> 5] = m;
    __syncthreads();
    if (t == 0) {
        float M = sb[0];
        #pragma unroll
        for (int k = 1; k < 8; k++) M = fmaxf(M, sb[k]);
        sM = M; g_R[r] = M;
    }
    __syncthreads();
    float M = sM;
    float4 e;
    e.x = __expf(z.x - M); e.y = __expf(z.y - M);
    e.z = __expf(z.z - M); e.w = __expf(z.w - M);
    ((float4*)(g_E + ((size_t)r << 10)))[t] = e;
}

__global__ void k_wexp() {
    int b = blockIdx.x, t = threadIdx.x;
    float4 v = ((const float4*)(g_v + (b << 10)))[t];
    float m = fmaxf(fmaxf(v.x, v.y), fmaxf(v.z, v.w));
    __shared__ float sb[8]; __shared__ float sV;
    #pragma unroll
    for (int o = 16; o; o >>= 1) m = fmaxf(m, __shfl_xor_sync(0xffffffffu, m, o));
    if ((t & 31) == 0) sb[t >> 5] = m;
    __syncthreads();
    if (t == 0) {
        float V = sb[0];
        #pragma unroll
        for (int k = 1; k < 8; k++) V = fmaxf(V, sb[k]);
        sV = V; g_Vb[b] = V;
    }
    __syncthreads();
    float V = sV;
    float4 w;
    w.x = __expf(v.x - V); w.y = __expf(v.y - V);
    w.z = __expf(v.z - V); w.w = __expf(v.w - V);
    ((float4*)(g_cw + (b << 10)))[t] = w;
}

__global__ void k_srow(const float* __restrict__ Z) {
    int r = blockIdx.x, b = r >> 10, t = threadIdx.x;
    float4 e = ((const float4*)(g_E + ((size_t)r << 10)))[t];
    float4 w = ((const float4*)(g_cw + (b << 10)))[t];
    float s = e.x*w.x + e.y*w.y + e.z*w.z + e.w*w.w;
    __shared__ float sb[8]; __shared__ float sS;
    #pragma unroll
    for (int o = 16; o; o >>= 1) s += __shfl_xor_sync(0xffffffffu, s, o);
    if ((t & 31) == 0) sb[t >> 5] = s;
    __syncthreads();
    if (t == 0) {
        float S = 0.0f;
        #pragma unroll
        for (int k = 0; k < 8; k++) S += sb[k];
        sS = S;
    }
    __syncthreads();
    float S = sS;
    if (S >= 1e-30f) {
        if (t == 0) g_u[r] = -(g_R[r] + g_Vb[b] + logf(S));
        return;
    }
    float4 z = ((const float4*)(Z + ((size_t)r << 10)))[t];
    float4 v = ((const float4*)(g_v + (b << 10)))[t];
    float a0 = z.x+v.x, a1 = z.y+v.y, a2 = z.z+v.z, a3 = z.w+v.w;
    float m = fmaxf(fmaxf(a0, a1), fmaxf(a2, a3));
    #pragma unroll
    for (int o = 16; o; o >>= 1) m = fmaxf(m, __shfl_xor_sync(0xffffffffu, m, o));
    if ((t & 31) == 0) sb[t >> 5] = m;
    __syncthreads();
    float M = sb[0];
    #pragma unroll
    for (int k = 1; k < 8; k++) M = fmaxf(M, sb[k]);
    __syncthreads();
    float s2 = __expf(a0-M) + __expf(a1-M) + __expf(a2-M) + __expf(a3-M);
    #pragma unroll
    for (int o = 16; o; o >>= 1) s2 += __shfl_xor_sync(0xffffffffu, s2, o);
    if ((t & 31) == 0) sb[t >> 5] = s2;
    __syncthreads();
    if (t == 0) {
        float S2 = 0.0f;
        #pragma unroll
        for (int k = 0; k < 8; k++) S2 += sb[k];
        g_u[r] = -(M + logf(S2));
    }
}

__global__ void k_yexp() {
    int b = blockIdx.x, t = threadIdx.x;
    float4 R = ((const float4*)(g_R + (b << 10)))[t];
    float4 u = ((const float4*)(g_u + (b << 10)))[t];
    float4 a; a.x = R.x+u.x; a.y = R.y+u.y; a.z = R.z+u.z; a.w = R.w+u.w;
    float m = fmaxf(fmaxf(a.x, a.y), fmaxf(a.z, a.w));
    __shared__ float sb[8]; __shared__ float sU;
    #pragma unroll
    for (int o = 16; o; o >>= 1) m = fmaxf(m, __shfl_xor_sync(0xffffffffu, m, o));
    if ((t & 31) == 0) sb[t >> 5] = m;
    __syncthreads();
    if (t == 0) {
        float U = sb[0];
        #pragma unroll
        for (int k = 1; k < 8; k++) U = fmaxf(U, sb[k]);
        sU = U; g_Ub[b] = U;
    }
    __syncthreads();
    float U = sU;
    float4 y;
    y.x = __expf(a.x - U); y.y = __expf(a.y - U);
    y.z = __expf(a.z - U); y.w = __expf(a.w - U);
    ((float4*)(g_y + (b << 10)))[t] = y;
}

__global__ void k_scol(const float* __restrict__ Z) {
    int b = blockIdx.y;
    int t = threadIdx.x, lane = t & 31, w = t >> 5;
    int col = blockIdx.x * 32 + lane;
    const float* Eb = g_E + ((size_t)b << 20);
    const float* yb = g_y + (b << 10);
    __shared__ float sm[8][32];
    __shared__ float tcol[32];
    __shared__ float mcol[32];
    float s = 0.0f;
    for (int i = w; i < NN; i += 8)
        s += Eb[((size_t)i << 10) + col] * yb[i];
    sm[w][lane] = s;
    __syncthreads();
    if (w == 0) {
        float ss = 0.0f;
        #pragma unroll
        for (int k = 0; k < 8; k++) ss += sm[k][lane];
        tcol[lane] = ss;
    }
    __syncthreads();
    float T = tcol[lane];
    float U = g_Ub[b];
    int anyslow = __syncthreads_or(T < 1e-30f);
    if (!anyslow) {
        if (w == 0) g_v[(b << 10) + col] = -(U + logf(T));
        return;
    }
    const float* Zb = Z + ((size_t)b << 20);
    const float* ub = g_u + (b << 10);
    float m = -1e30f;
    for (int i = w; i < NN; i += 8)
        m = fmaxf(m, Zb[((size_t)i << 10) + col] + ub[i]);
    sm[w][lane] = m;
    __syncthreads();
    if (w == 0) {
        float mm = sm[0][lane];
        #pragma unroll
        for (int k = 1; k < 8; k++) mm = fmaxf(mm, sm[k][lane]);
        mcol[lane] = mm;
    }
    __syncthreads();
    float M = mcol[lane];
    float s2 = 0.0f;
    for (int i = w; i < NN; i += 8)
        s2 += __expf(Zb[((size_t)i << 10) + col] + ub[i] - M);
    sm[w][lane] = s2;
    __syncthreads();
    if (w == 0) {
        float ss2 = 0.0f;
        #pragma unroll
        for (int k = 0; k < 8; k++) ss2 += sm[k][lane];
        float res = (T < 1e-30f) ? -(M + logf(ss2)) : -(U + logf(T));
        g_v[(b << 10) + col] = res;
    }
}

// ---------------- finalization -------------------------------------------
__global__ void k_final_row(const float* __restrict__ Z) {
    int r = blockIdx.x, b = r >> 10, t = threadIdx.x;
    const float4* z4 = (const float4*)(Z + ((size_t)r << 10));
    const float4* v4 = (const float4*)(g_v + (b << 10));
    float uu = g_u[r];
    float4 z = z4[t], v = v4[t], e;
    e.x = __expf(z.x + uu + v.x); e.y = __expf(z.y + uu + v.y);
    e.z = __expf(z.z + uu + v.z); e.w = __expf(z.w + uu + v.w);
    ((float4*)(g_P + ((size_t)r << 10)))[t] = e;
    float s = e.x + e.y + e.z + e.w;
    __shared__ float sb[8];
    #pragma unroll
    for (int o = 16; o; o >>= 1) s += __shfl_xor_sync(0xffffffffu, s, o);
    if ((t & 31) == 0) sb[t >> 5] = s;
    __syncthreads();
    if (t == 0) {
        float S = 0.0f;
        #pragma unroll
        for (int k = 0; k < 8; k++) S += sb[k];
        g_r[r] = 1.0f / S;
    }
}

__global__ void k_final_col() {
    int b = blockIdx.y;
    int lane = threadIdx.x & 31, w = threadIdx.x >> 5;
    int col = blockIdx.x * 32 + lane;
    const float* Pb = g_P + ((size_t)b << 20);
    const float* rb = g_r + (b << 10);
    __shared__ float sm[8][32];
    float s = 0.0f;
    for (int i = w; i < NN; i += 8)
        s += Pb[((size_t)i << 10) + col] * rb[i];
    sm[w][lane] = s;
    __syncthreads();
    if (w == 0) {
        float ss = 0.0f;
        #pragma unroll
        for (int k = 0; k < 8; k++) ss += sm[k][lane];
        g_c[(b << 10) + col] = 1.0f / ss;
    }
}

__global__ void k_writeP(float* __restrict__ outp) {
    int r = blockIdx.x, b = r >> 10, t = threadIdx.x;
    float ri = g_r[r];
    float4 pv = ((const float4*)(g_P + ((size_t)r << 10)))[t];
    float4 cv = ((const float4*)(g_c + (b << 10)))[t];
    float4 o;
    o.x = pv.x * ri * cv.x; o.y = pv.y * ri * cv.y;
    o.z = pv.z * ri * cv.z; o.w = pv.w * ri * cv.w;
    ((float4*)outp)[((size_t)r << 8) + t] = o;
}

__global__ void k_copyZ(float* __restrict__ outp) {
    int r = blockIdx.x, t = threadIdx.x;
    float4 z = ((const float4*)(g_Z0 + ((size_t)r << 10)))[t];
    ((float4*)outp)[((size_t)r << 8) + t] = z;
}

__global__ void k_zero(float* __restrict__ p) {
    p[blockIdx.x * 1024 + threadIdx.x] = 0.0f;
}

// ---------------- host ----------------------------------------------------
extern "C" void kernel_launch(void* const* d_in, const int* in_sizes, int n_in,
                              void* d_out, int out_size) {
    const float* X    = (const float*)d_in[0];
    const float* adj  = (const float*)d_in[1];
    const float* w_in = (const float*)d_in[2];
    const float* b_in = (const float*)d_in[3];
    const float* cw1  = (const float*)d_in[4];
    const float* cb1  = (const float*)d_in[5];
    const float* cw2  = (const float*)d_in[6];
    const float* cb2  = (const float*)d_in[7];
    const float* ca   = (const float*)d_in[8];
    const float* m1w  = (const float*)d_in[9];
    const float* m1b  = (const float*)d_in[10];
    const float* m2w  = (const float*)d_in[11];
    const float* m2b  = (const float*)d_in[12];
    float* out = (float*)d_out;

    float *hcat, *g0, *p1, *p2, *p3, *p4, *hp, *tmp, *mlp, *Z0, *vv;
    cudaGetSymbolAddress((void**)&hcat, g_Hcat);
    cudaGetSymbolAddress((void**)&g0,   g_g0);
    cudaGetSymbolAddress((void**)&p1,   g_p1);
    cudaGetSymbolAddress((void**)&p2,   g_p2);
    cudaGetSymbolAddress((void**)&p3,   g_p3);
    cudaGetSymbolAddress((void**)&p4,   g_p4);
    cudaGetSymbolAddress((void**)&hp,   g_hp);
    cudaGetSymbolAddress((void**)&tmp,  g_tmp);
    cudaGetSymbolAddress((void**)&mlp,  g_mlp);
    cudaGetSymbolAddress((void**)&Z0,   g_Z0);
    cudaGetSymbolAddress((void**)&vv,   g_v);

    dim3 gN(2, 128);          // N=256 outputs, M=16384
    dim3 gZ(8, 128);          // N=1024 outputs
    dim3 gA(2, 8, 16);        // adj GEMM per batch
    dim3 gC(32, 16);          // column passes

    k_adj_stats<<<ROWS, 256>>>(adj);
    k_gemm<<<gN, 256>>>(X, 128, 128, w_in, b_in, hcat, 768, 0);

    for (int l = 0; l < 2; l++) {
        const float* Xl = hcat + l * 256;
        k_adjmm<<<gA, 256>>>(adj, Xl, 768, g0, 0);
        k_adjmm<<<gA, 256>>>(adj, Xl, 768, p1, 1);
        k_adjmm<<<gA, 256>>>(adj, p1, 256, p2, 1);
        k_adjmm<<<gA, 256>>>(adj, p2, 256, p3, 1);
        k_adjmm<<<gA, 256>>>(adj, p3, 256, p4, 1);
        k_attn<<<ROWS, 256>>>(Xl, ca + l * 512 + 256);
        k_gemm<<<gN, 256>>>(hp, 256, 256, cw1 + l * 65536, cb1 + l * 256, tmp, 256, 1);
        k_gemm<<<gN, 256>>>(tmp, 256, 256, cw2 + l * 65536, cb2 + l * 256,
                            hcat + (l + 1) * 256, 768, 1);
    }
    k_gemm<<<gN, 256>>>(hcat, 768, 768, m1w, m1b, mlp, 256, 1);
    k_gemm<<<gZ, 256>>>(mlp, 256, 256, m2w, m2b, Z0, 1024, 2);

    // Sinkhorn (linear-domain iterations over E with potentials)
    k_zero<<<16, 1024>>>(vv);
    k_prep<<<ROWS, 256>>>(Z0);
    for (int it = 0; it < 20; it++) {
        k_wexp<<<NB, 256>>>();
        k_srow<<<ROWS, 256>>>(Z0);
        k_yexp<<<NB, 256>>>();
        k_scol<<<gC, 256>>>(Z0);
    }
    k_final_row<<<ROWS, 256>>>(Z0);
    k_final_col<<<gC, 256>>>();
    k_writeP<<<ROWS, 256>>>(out);
    if (out_size >= 2 * ZELEMS)
        k_copyZ<<<ROWS, 256>>>(out + ZELEMS);
}